// round 16
// baseline (speedup 1.0000x reference)
#include <cuda_runtime.h>
#include <cuda_fp16.h>
#include <cuda_bf16.h>
#include <cstdint>

#define ND   256
#define CD   512
#define OD   128
#define HID  64
#define NB   64
#define NMAX 100000
#define EMAX 1600000

// -------- device scratch --------
__device__ __align__(16) __half g_xh[NMAX * OD];      // node feats (fp16)
__device__ __align__(16) uint4 g_fwf[64 * 16 * 4];    // film_w bf16-split fragments
__device__ __align__(16) uint4 g_lwf[128 * 4 * 4];    // normalized lin_w split fragments
__device__ float g_gamma[NB * HID];
__device__ float g_beta[NB * HID];
__device__ int g_cnt[NMAX];          // zero-initialized at load; re-zeroed by k_gather
__device__ int g_excl[NMAX];
__device__ int g_start[NMAX];
__device__ int g_pos[NMAX];
__device__ int g_srcs[EMAX];
__device__ int g_bsum[128];
__device__ const float* d_gainp[2];
__device__ const float* d_biasp[2];
__device__ int d_n2g64;

// ---- bf16 helpers ----
__device__ __forceinline__ uint32_t pack_bf16(__nv_bfloat16 a, __nv_bfloat16 b) {
    __nv_bfloat162 p = __halves2bfloat162(a, b);
    return *reinterpret_cast<uint32_t*>(&p);
}
__device__ __forceinline__ void bf16_split2(float f0, float f1, uint32_t& hi, uint32_t& lo) {
    __nv_bfloat16 h0 = __float2bfloat16(f0);
    __nv_bfloat16 h1 = __float2bfloat16(f1);
    float r0 = f0 - __bfloat162float(h0);
    float r1 = f1 - __bfloat162float(h1);
    hi = pack_bf16(h0, h1);
    lo = pack_bf16(__float2bfloat16(r0), __float2bfloat16(r1));
}
__device__ __forceinline__ void mma_bf16(float& d0, float& d1, float& d2, float& d3,
                                         uint32_t a0, uint32_t a1, uint32_t a2, uint32_t a3,
                                         uint32_t b0, uint32_t b1) {
    asm volatile(
        "mma.sync.aligned.m16n8k16.row.col.f32.bf16.bf16.f32 "
        "{%0,%1,%2,%3}, {%4,%5,%6,%7}, {%8,%9}, {%0,%1,%2,%3};"
        : "+f"(d0), "+f"(d1), "+f"(d2), "+f"(d3)
        : "r"(a0), "r"(a1), "r"(a2), "r"(a3), "r"(b0), "r"(b1));
}
__device__ __forceinline__ void ldm_x4(uint32_t& r0, uint32_t& r1, uint32_t& r2, uint32_t& r3,
                                       uint32_t addr) {
    asm volatile("ldmatrix.sync.aligned.m8n8.x4.shared.b16 {%0,%1,%2,%3}, [%4];"
                 : "=r"(r0), "=r"(r1), "=r"(r2), "=r"(r3) : "r"(addr));
}

#define ASTR 72

// block-local edge-index dtype detect (odd int32 slots all zero iff int64)
__device__ __forceinline__ int detect_ei64(const int* ei32, int* s_or) {
    if (threadIdx.x == 0) *s_or = 0;
    __syncthreads();
    if (threadIdx.x < 64) atomicOr(s_or, ei32[2 * threadIdx.x + 1]);
    __syncthreads();
    return (*s_or == 0) ? 1 : 0;
}

// ============================================================
// prep: single block — classify + weight pre-split
// ============================================================
__global__ void __launch_bounds__(256) k_prep(
    const float* q0, const float* q1, const float* q2, const float* q3,
    const int* n2g32, int N,
    const float* __restrict__ lin_wv,    // [128, 64]
    const float* __restrict__ film_w)    // [64, 256]
{
    int t = threadIdx.x;
    __shared__ int scnt[4];
    __shared__ int sor;
    __shared__ const float* sg[2];
    __shared__ const float* sb[2];
    __shared__ float s_scale[128];
    if (t < 4) scnt[t] = 0;
    if (t == 0) sor = 0;
    __syncthreads();
    const float* qs[4] = {q0, q1, q2, q3};
    if (t < 128) {
        #pragma unroll
        for (int j = 0; j < 4; j++)
            if (qs[j][t] < 0.3f) atomicAdd(&scnt[j], 1);
    }
    if (t < 32) {
        int st = (N - 2) | 1;
        atomicOr(&sor, n2g32[st - 2 * t]);
    }
    __syncthreads();
    if (t == 0) {
        int gi = 0, bi = 0;
        #pragma unroll
        for (int j = 0; j < 4; j++) {
            if (scnt[j] > 64) { if (bi < 2) sb[bi++] = qs[j]; }
            else              { if (gi < 2) sg[gi++] = qs[j]; }
        }
        if (gi < 2) { sg[0] = q0; sg[1] = q2; }
        if (bi < 2) { sb[0] = q1; sb[1] = q3; }
        d_gainp[0] = sg[0]; d_gainp[1] = sg[1];
        d_biasp[0] = sb[0]; d_biasp[1] = sb[1];
        d_n2g64 = (sor == 0) ? 1 : 0;
    }
    __syncthreads();
    if (t < 128) {
        const float* wr = lin_wv + t * HID;
        float s2 = 0.f;
        #pragma unroll 8
        for (int k = 0; k < HID; k++) { float v = wr[k]; s2 += v * v; }
        s_scale[t] = sg[1][t] * rsqrtf(s2);
    }
    __syncthreads();
    for (int e = t; e < 128 * 4 * 4; e += 256) {
        int lc = e & 3;
        int kb16 = (e >> 2) & 3;
        int n = e >> 4;
        int k0 = kb16 * 16 + 2 * lc;
        float sc = s_scale[n];
        uint32_t bh0, bl0, bh1, bl1;
        bf16_split2(lin_wv[n * HID + k0] * sc,     lin_wv[n * HID + k0 + 1] * sc, bh0, bl0);
        bf16_split2(lin_wv[n * HID + k0 + 8] * sc, lin_wv[n * HID + k0 + 9] * sc, bh1, bl1);
        g_lwf[e] = make_uint4(bh0, bh1, bl0, bl1);
    }
    for (int e = t; e < 64 * 16 * 4; e += 256) {
        int lc = e & 3;
        int kb16 = (e >> 2) & 15;
        int n = e >> 6;
        int k0 = kb16 * 16 + 2 * lc;
        uint32_t bh0, bl0, bh1, bl1;
        bf16_split2(film_w[n * ND + k0],     film_w[n * ND + k0 + 1], bh0, bl0);
        bf16_split2(film_w[n * ND + k0 + 8], film_w[n * ND + k0 + 9], bh1, bl1);
        g_fwf[e] = make_uint4(bh0, bh1, bl0, bl1);
    }
}

// ============================================================
// cond projection (self-classifying) -> gamma/beta. grid=(128,8)
// ============================================================
__global__ void __launch_bounds__(256) k_cond(
    const float* __restrict__ cf,
    const float* __restrict__ wv,
    const float* q0, const float* q1, const float* q2, const float* q3)
{
    int o = blockIdx.x;
    int t = threadIdx.x;
    __shared__ float sw[CD];
    __shared__ float red[8];
    __shared__ int scnt[4];
    __shared__ const float* sgb[2];   // [0]=cond gain, [1]=cond bias
    const float* wr = wv + o * CD;

    if (t < 4) scnt[t] = 0;
    __syncthreads();
    const float* qs[4] = {q0, q1, q2, q3};
    if (t < 128) {
        #pragma unroll
        for (int j = 0; j < 4; j++)
            if (qs[j][t] < 0.3f) atomicAdd(&scnt[j], 1);
    }
    float s2 = 0.f;
    for (int k = t; k < CD; k += 256) { float v = wr[k]; sw[k] = v; s2 += v * v; }
    #pragma unroll
    for (int d = 16; d; d >>= 1) s2 += __shfl_xor_sync(0xFFFFFFFFu, s2, d);
    if ((t & 31) == 0) red[t >> 5] = s2;
    __syncthreads();
    if (t == 0) {
        const float* g0 = 0; const float* b0 = 0;
        #pragma unroll
        for (int j = 0; j < 4; j++) {
            if (scnt[j] > 64) { if (!b0) b0 = qs[j]; }
            else              { if (!g0) g0 = qs[j]; }
        }
        sgb[0] = g0 ? g0 : q0;
        sgb[1] = b0 ? b0 : q1;
    }
    __syncthreads();
    float norm2 = red[0] + red[1] + red[2] + red[3] + red[4] + red[5] + red[6] + red[7];
    float scale = sgb[0][o] * rsqrtf(norm2);
    float bias  = sgb[1][o];

    const int w = t >> 5, lane = t & 31;
    int row = blockIdx.y * 8 + w;
    const float* cfr = cf + row * CD;
    float acc = 0.f;
    #pragma unroll
    for (int k = lane; k < CD; k += 32) acc += cfr[k] * sw[k];
    #pragma unroll
    for (int d = 16; d; d >>= 1) acc += __shfl_xor_sync(0xFFFFFFFFu, acc, d);
    if (lane == 0) {
        float val = acc * scale + bias;
        if (o < HID) g_gamma[row * HID + o] = val + 1.0f;
        else         g_beta[row * HID + (o - HID)] = val;
    }
}

// ============================================================
// node transform: pre-split bf16 A planes + ldmatrix, bf16x3 MMA
// ============================================================
__global__ void __launch_bounds__(256) k_node(
    const float* __restrict__ feats,
    const float* __restrict__ film_b,
    const void*  __restrict__ n2g,
    int nNodes)
{
    __shared__ __align__(16) char sm[36864];

    const int t = threadIdx.x;
    const int node0 = blockIdx.x * 64;
    const int w = t >> 5, lane = t & 31;
    const int mg = w >> 1, ng = w & 1;
    const int lr = lane >> 2, lc = lane & 3;
    const int srow = t >> 4, sc4 = t & 15;

    const uint32_t smb = (uint32_t)__cvta_generic_to_shared(sm);
    const int lmRow = ((lane >> 3) & 1) * 8 + (lane & 7);
    const int lmCol = (lane >> 4) * 8;

    float c[4][4];
    #pragma unroll
    for (int j = 0; j < 4; j++)
        #pragma unroll
        for (int i = 0; i < 4; i++) c[j][i] = 0.f;

    auto stage_store = [&](int b, int row, int c0, float4 va) {
        uint32_t h01, l01, h23, l23;
        bf16_split2(va.x, va.y, h01, l01);
        bf16_split2(va.z, va.w, h23, l23);
        char* hp = sm + b * 18432 + (row * ASTR + c0) * 2;
        char* lp = hp + 9216;
        *(uint2*)hp = make_uint2(h01, h23);
        *(uint2*)lp = make_uint2(l01, l23);
    };

    #pragma unroll
    for (int it = 0; it < 4; it++) {
        int row = srow + it * 16;
        float4 va = (node0 + row < nNodes)
            ? *(const float4*)(feats + (size_t)(node0 + row) * ND + sc4 * 4)
            : make_float4(0.f, 0.f, 0.f, 0.f);
        stage_store(0, row, sc4 * 4, va);
    }
    __syncthreads();

    #pragma unroll
    for (int ch = 0; ch < 4; ch++) {
        const int b = ch & 1;
        float4 pf[4];
        if (ch < 3) {
            #pragma unroll
            for (int it = 0; it < 4; it++) {
                int row = srow + it * 16;
                int gk  = (ch + 1) * 64 + sc4 * 4;
                pf[it] = (node0 + row < nNodes)
                    ? *(const float4*)(feats + (size_t)(node0 + row) * ND + gk)
                    : make_float4(0.f, 0.f, 0.f, 0.f);
            }
        }
        #pragma unroll
        for (int kb = 0; kb < 4; kb++) {
            uint32_t aBase = smb + b * 18432
                           + ((mg * 16 + lmRow) * ASTR + kb * 16 + lmCol) * 2;
            uint32_t ah0, ah1, ah2, ah3, al0, al1, al2, al3;
            ldm_x4(ah0, ah1, ah2, ah3, aBase);
            ldm_x4(al0, al1, al2, al3, aBase + 9216);
            int gkb16 = ch * 4 + kb;
            #pragma unroll
            for (int j = 0; j < 4; j++) {
                int bn = ng * 32 + j * 8 + lr;
                uint4 B = __ldg(&g_fwf[(bn * 16 + gkb16) * 4 + lc]);
                mma_bf16(c[j][0], c[j][1], c[j][2], c[j][3], ah0, ah1, ah2, ah3, B.x, B.y);
                mma_bf16(c[j][0], c[j][1], c[j][2], c[j][3], ah0, ah1, ah2, ah3, B.z, B.w);
                mma_bf16(c[j][0], c[j][1], c[j][2], c[j][3], al0, al1, al2, al3, B.x, B.y);
            }
        }
        // double-buffer: target buf was fully consumed in iteration ch-1
        // (guarded by the loop-end sync), so no extra sync before storing.
        if (ch < 3) {
            #pragma unroll
            for (int it = 0; it < 4; it++)
                stage_store((ch + 1) & 1, srow + it * 16, sc4 * 4, pf[it]);
        }
        __syncthreads();
    }

    float* sH = (float*)sm;
    {
        int row0 = mg * 16 + lr;
        #pragma unroll
        for (int j = 0; j < 4; j++) {
            int cb = ng * 32 + j * 8 + 2 * lc;
            sH[row0 * 68 + cb]           = c[j][0] + __ldg(&film_b[cb]);
            sH[row0 * 68 + cb + 1]       = c[j][1] + __ldg(&film_b[cb + 1]);
            sH[(row0 + 8) * 68 + cb]     = c[j][2] + __ldg(&film_b[cb]);
            sH[(row0 + 8) * 68 + cb + 1] = c[j][3] + __ldg(&film_b[cb + 1]);
        }
    }
    __syncthreads();

    // ---- LayerNorm + FiLM + relu -> bf16 hi/lo planes for GEMM2 ----
    {
        __nv_bfloat16* hi2 = (__nv_bfloat16*)(sm + 18432);
        __nv_bfloat16* lo2 = (__nv_bfloat16*)(sm + 27648);
        const int is64 = d_n2g64;
        #pragma unroll
        for (int r = 0; r < 8; r++) {
            int i = w * 8 + r;
            int node = node0 + i;
            float v0 = sH[i * 68 + lane];
            float v1 = sH[i * 68 + 32 + lane];
            float s = v0 + v1;
            #pragma unroll
            for (int d = 16; d; d >>= 1) s += __shfl_xor_sync(0xFFFFFFFFu, s, d);
            float mu = s * (1.0f / 64.0f);
            float d0 = v0 - mu, d1 = v1 - mu;
            float q = d0 * d0 + d1 * d1;
            #pragma unroll
            for (int d = 16; d; d >>= 1) q += __shfl_xor_sync(0xFFFFFFFFu, q, d);
            float rstd = rsqrtf(q * (1.0f / 64.0f) + 1e-5f);
            int idx = (node < nNodes) ? node : 0;
            int g = is64 ? (int)((const long long*)n2g)[idx]
                         : ((const int*)n2g)[idx];
            g &= (NB - 1);
            const float* gp = g_gamma + g * HID;
            const float* bp = g_beta + g * HID;
            float y0 = fmaxf(gp[lane]      * (d0 * rstd) + bp[lane],      0.f);
            float y1 = fmaxf(gp[lane + 32] * (d1 * rstd) + bp[lane + 32], 0.f);
            __nv_bfloat16 h0 = __float2bfloat16(y0);
            __nv_bfloat16 h1 = __float2bfloat16(y1);
            hi2[i * ASTR + lane]      = h0;
            hi2[i * ASTR + 32 + lane] = h1;
            lo2[i * ASTR + lane]      = __float2bfloat16(y0 - __bfloat162float(h0));
            lo2[i * ASTR + 32 + lane] = __float2bfloat16(y1 - __bfloat162float(h1));
        }
    }
    __syncthreads();

    // ---- GEMM2 ----
    {
        float c2[8][4];
        #pragma unroll
        for (int j = 0; j < 8; j++)
            #pragma unroll
            for (int i = 0; i < 4; i++) c2[j][i] = 0.f;

        #pragma unroll
        for (int kb = 0; kb < 4; kb++) {
            uint32_t aBase = smb + 18432
                           + ((mg * 16 + lmRow) * ASTR + kb * 16 + lmCol) * 2;
            uint32_t ah0, ah1, ah2, ah3, al0, al1, al2, al3;
            ldm_x4(ah0, ah1, ah2, ah3, aBase);
            ldm_x4(al0, al1, al2, al3, aBase + 9216);
            #pragma unroll
            for (int j = 0; j < 8; j++) {
                int bn = ng * 64 + j * 8 + lr;
                uint4 B = __ldg(&g_lwf[(bn * 4 + kb) * 4 + lc]);
                mma_bf16(c2[j][0], c2[j][1], c2[j][2], c2[j][3], ah0, ah1, ah2, ah3, B.x, B.y);
                mma_bf16(c2[j][0], c2[j][1], c2[j][2], c2[j][3], ah0, ah1, ah2, ah3, B.z, B.w);
                mma_bf16(c2[j][0], c2[j][1], c2[j][2], c2[j][3], al0, al1, al2, al3, B.x, B.y);
            }
        }
        const float* lb = d_biasp[1];
        __half2* xh2 = (__half2*)g_xh;
        int r0 = node0 + mg * 16 + lr;
        #pragma unroll
        for (int j = 0; j < 8; j++) {
            int cb = ng * 64 + j * 8 + 2 * lc;
            float b0 = __ldg(&lb[cb]), b1 = __ldg(&lb[cb + 1]);
            if (r0 < nNodes)
                xh2[(size_t)r0 * 64 + (cb >> 1)] =
                    __floats2half2_rn(c2[j][0] + b0, c2[j][1] + b1);
            if (r0 + 8 < nNodes)
                xh2[(size_t)(r0 + 8) * 64 + (cb >> 1)] =
                    __floats2half2_rn(c2[j][2] + b0, c2[j][3] + b1);
        }
    }
}

// ============================================================
// CSR build (dependency-free of prep)
// ============================================================
__global__ void k_hist(const void* __restrict__ eiv, int E, int nNodes) {
    __shared__ int s_or;
    int is64 = detect_ei64((const int*)eiv, &s_or);
    int e = blockIdx.x * blockDim.x + threadIdx.x;
    if (e >= E) return;
    int dst = is64 ? (int)((const long long*)eiv)[(size_t)E + e]
                   : ((const int*)eiv)[(size_t)E + e];
    if ((unsigned)dst < (unsigned)nNodes) atomicAdd(&g_cnt[dst], 1);
}

__global__ void __launch_bounds__(1024) k_scan1(int n) {
    __shared__ int s[1024];
    int i = blockIdx.x * 1024 + threadIdx.x;
    int v = (i < n) ? g_cnt[i] : 0;
    s[threadIdx.x] = v;
    __syncthreads();
    #pragma unroll
    for (int d = 1; d < 1024; d <<= 1) {
        int t = (threadIdx.x >= d) ? s[threadIdx.x - d] : 0;
        __syncthreads();
        s[threadIdx.x] += t;
        __syncthreads();
    }
    if (i < n) g_excl[i] = s[threadIdx.x] - v;
    if (threadIdx.x == 1023) g_bsum[blockIdx.x] = s[1023];
}

__global__ void __launch_bounds__(256) k_scan3(int n) {
    __shared__ int sbase;
    int seg = (blockIdx.x * 256) >> 10;
    if (threadIdx.x < 32) {
        int partial = 0;
        for (int k = threadIdx.x; k < seg; k += 32) partial += g_bsum[k];
        #pragma unroll
        for (int d = 16; d; d >>= 1) partial += __shfl_xor_sync(0xFFFFFFFFu, partial, d);
        if (threadIdx.x == 0) sbase = partial;
    }
    __syncthreads();
    int i = blockIdx.x * 256 + threadIdx.x;
    if (i >= n) return;
    int st = g_excl[i] + sbase;
    g_start[i] = st;
    g_pos[i] = st;
}

__global__ void k_fill(const void* __restrict__ eiv, int E, int nNodes) {
    __shared__ int s_or;
    int is64 = detect_ei64((const int*)eiv, &s_or);
    int e = blockIdx.x * blockDim.x + threadIdx.x;
    if (e >= E) return;
    int src, dst;
    if (is64) {
        const long long* ei = (const long long*)eiv;
        src = (int)ei[e];
        dst = (int)ei[(size_t)E + e];
    } else {
        const int* ei = (const int*)eiv;
        src = ei[e];
        dst = ei[(size_t)E + e];
    }
    if ((unsigned)src >= (unsigned)nNodes || (unsigned)dst >= (unsigned)nNodes) return;
    int p = atomicAdd(&g_pos[dst], 1);
    g_srcs[p] = src;
}

// ============================================================
// gather: one warp per destination node; re-zeroes g_cnt for next call
// ============================================================
__global__ void __launch_bounds__(256) k_gather(float4* __restrict__ out4, int nNodes) {
    int warp = (blockIdx.x * blockDim.x + threadIdx.x) >> 5;
    if (warp >= nNodes) return;
    int lane = threadIdx.x & 31;
    int start = g_start[warp];
    int deg = g_cnt[warp];
    if (lane == 0) g_cnt[warp] = 0;   // reset for next call (deterministic invariant)
    const uint2* x2 = (const uint2*)g_xh;

    float4 acc = make_float4(0.f, 0.f, 0.f, 0.f);
    int j = 0;
    for (; j + 8 <= deg; j += 8) {
        int ss[8];
        #pragma unroll
        for (int u = 0; u < 8; u++) ss[u] = __ldg(&g_srcs[start + j + u]);
        uint2 uu[8];
        #pragma unroll
        for (int u = 0; u < 8; u++) uu[u] = __ldg(&x2[(size_t)ss[u] * 32 + lane]);
        #pragma unroll
        for (int u = 0; u < 8; u++) {
            float2 a = __half22float2(*(__half2*)&uu[u].x);
            float2 b = __half22float2(*(__half2*)&uu[u].y);
            acc.x += a.x; acc.y += a.y; acc.z += b.x; acc.w += b.y;
        }
    }
    for (; j + 4 <= deg; j += 4) {
        int ss[4];
        #pragma unroll
        for (int u = 0; u < 4; u++) ss[u] = __ldg(&g_srcs[start + j + u]);
        uint2 uu[4];
        #pragma unroll
        for (int u = 0; u < 4; u++) uu[u] = __ldg(&x2[(size_t)ss[u] * 32 + lane]);
        #pragma unroll
        for (int u = 0; u < 4; u++) {
            float2 a = __half22float2(*(__half2*)&uu[u].x);
            float2 b = __half22float2(*(__half2*)&uu[u].y);
            acc.x += a.x; acc.y += a.y; acc.z += b.x; acc.w += b.y;
        }
    }
    for (; j < deg; j++) {
        int s0 = __ldg(&g_srcs[start + j]);
        uint2 u0 = __ldg(&x2[(size_t)s0 * 32 + lane]);
        float2 a0 = __half22float2(*(__half2*)&u0.x), b0 = __half22float2(*(__half2*)&u0.y);
        acc.x += a0.x; acc.y += a0.y; acc.z += b0.x; acc.w += b0.y;
    }
    float s = 1.0f / (float)max(deg, 1);
    float4 o;
    o.x = fmaxf(acc.x * s, 0.f);
    o.y = fmaxf(acc.y * s, 0.f);
    o.z = fmaxf(acc.z * s, 0.f);
    o.w = fmaxf(acc.w * s, 0.f);
    out4[(size_t)warp * 32 + lane] = o;
}

// ============================================================
extern "C" void kernel_launch(void* const* d_in, const int* in_sizes, int n_in,
                              void* d_out, int out_size)
{
    const float *node_feats = 0, *cond_feats = 0, *cond_w_v = 0;
    const float *film_w = 0, *film_b = 0, *lin_w_v = 0;
    const void  *edge_index = 0, *node2graph = 0;
    const float *quad[4] = {0, 0, 0, 0};
    int nq = 0;
    int nNodes = NMAX, E = EMAX;

    for (int i = 0; i < n_in; i++) {
        int s = in_sizes[i];
        const void* p = d_in[i];
        switch (s) {
            case NMAX * ND:   node_feats = (const float*)p; nNodes = s / ND; break;
            case 2 * EMAX:    edge_index = p; E = s / 2; break;
            case OD * CD:     cond_w_v   = (const float*)p; break;
            case NB * CD:     cond_feats = (const float*)p; break;
            case HID * ND:    film_w     = (const float*)p; break;
            case OD * HID:    lin_w_v    = (const float*)p; break;
            case NMAX:        node2graph = p; break;
            case HID:         film_b     = (const float*)p; break;
            case OD:          if (nq < 4) quad[nq++] = (const float*)p; break;
            default: break;
        }
    }
    if (!node_feats || !edge_index || !node2graph || nq < 4) return;

    float* out = (float*)d_out;

    static cudaStream_t s_aux = 0;
    static cudaEvent_t s_ev0 = 0, s_ev1 = 0;
    static int s_tried = 0;
    if (!s_tried) {
        s_tried = 1;
        if (cudaStreamCreateWithFlags(&s_aux, cudaStreamNonBlocking) != cudaSuccess) s_aux = 0;
        if (s_aux) {
            if (cudaEventCreateWithFlags(&s_ev0, cudaEventDisableTiming) != cudaSuccess) s_ev0 = 0;
            if (cudaEventCreateWithFlags(&s_ev1, cudaEventDisableTiming) != cudaSuccess) s_ev1 = 0;
            if (!s_ev0 || !s_ev1) s_aux = 0;
        }
    }

    const int nodeBlocks = (nNodes + 63) / 64;
    const int histBlocks = (E + 255) / 256;
    const int nb = (nNodes + 1023) / 1024;
    dim3 condGrid(OD, 8);
    const long long gwork = (long long)nNodes * 32;
    const int gatherBlocks = (int)((gwork + 255) / 256);

    if (s_aux) {
        // fork immediately: aux branch has zero dependencies on main
        cudaEventRecord(s_ev0, 0);
        cudaStreamWaitEvent(s_aux, s_ev0, 0);
        k_hist<<<histBlocks, 256, 0, s_aux>>>(edge_index, E, nNodes);
        k_scan1<<<nb, 1024, 0, s_aux>>>(nNodes);
        k_scan3<<<(nNodes + 255) / 256, 256, 0, s_aux>>>(nNodes);
        k_fill<<<histBlocks, 256, 0, s_aux>>>(edge_index, E, nNodes);
        cudaEventRecord(s_ev1, s_aux);
        // main branch
        k_cond<<<condGrid, 256>>>(cond_feats, cond_w_v,
                                  quad[0], quad[1], quad[2], quad[3]);
        k_prep<<<1, 256>>>(quad[0], quad[1], quad[2], quad[3],
                           (const int*)node2graph, nNodes, lin_w_v, film_w);
        k_node<<<nodeBlocks, 256>>>(node_feats, film_b, node2graph, nNodes);
        cudaStreamWaitEvent(0, s_ev1, 0);
        k_gather<<<gatherBlocks, 256>>>((float4*)out, nNodes);
    } else {
        k_cond<<<condGrid, 256>>>(cond_feats, cond_w_v,
                                  quad[0], quad[1], quad[2], quad[3]);
        k_prep<<<1, 256>>>(quad[0], quad[1], quad[2], quad[3],
                           (const int*)node2graph, nNodes, lin_w_v, film_w);
        k_hist<<<histBlocks, 256>>>(edge_index, E, nNodes);
        k_scan1<<<nb, 1024>>>(nNodes);
        k_scan3<<<(nNodes + 255) / 256, 256>>>(nNodes);
        k_fill<<<histBlocks, 256>>>(edge_index, E, nNodes);
        k_node<<<nodeBlocks, 256>>>(node_feats, film_b, node2graph, nNodes);
        k_gather<<<gatherBlocks, 256>>>((float4*)out, nNodes);
    }
}

// round 17
// speedup vs baseline: 1.2684x; 1.2684x over previous
#include <cuda_runtime.h>
#include <cuda_fp16.h>
#include <cuda_bf16.h>
#include <cstdint>

#define ND   256
#define CD   512
#define OD   128
#define HID  64
#define NB   64
#define NMAX 100000
#define EMAX 1600000

// -------- device scratch --------
__device__ __align__(16) __half g_xh[NMAX * OD];      // node feats (fp16)
__device__ __align__(16) uint4 g_fwf[64 * 16 * 4];    // film_w bf16-split fragments
__device__ __align__(16) uint4 g_lwf[128 * 4 * 4];    // normalized lin_w split fragments
__device__ float g_gamma[NB * HID];
__device__ float g_beta[NB * HID];
__device__ int g_cnt[NMAX];
__device__ int g_excl[NMAX];
__device__ int g_start[NMAX];
__device__ int g_pos[NMAX];
__device__ int g_srcs[EMAX];
__device__ int g_bsum[128];
__device__ const float* d_gainp[2];
__device__ const float* d_biasp[2];
__device__ int d_ei64;
__device__ int d_n2g64;

// ---- bf16 helpers ----
__device__ __forceinline__ uint32_t pack_bf16(__nv_bfloat16 a, __nv_bfloat16 b) {
    __nv_bfloat162 p = __halves2bfloat162(a, b);
    return *reinterpret_cast<uint32_t*>(&p);
}
__device__ __forceinline__ void bf16_split2(float f0, float f1, uint32_t& hi, uint32_t& lo) {
    __nv_bfloat16 h0 = __float2bfloat16(f0);
    __nv_bfloat16 h1 = __float2bfloat16(f1);
    float r0 = f0 - __bfloat162float(h0);
    float r1 = f1 - __bfloat162float(h1);
    hi = pack_bf16(h0, h1);
    lo = pack_bf16(__float2bfloat16(r0), __float2bfloat16(r1));
}
__device__ __forceinline__ void mma_bf16(float& d0, float& d1, float& d2, float& d3,
                                         uint32_t a0, uint32_t a1, uint32_t a2, uint32_t a3,
                                         uint32_t b0, uint32_t b1) {
    asm volatile(
        "mma.sync.aligned.m16n8k16.row.col.f32.bf16.bf16.f32 "
        "{%0,%1,%2,%3}, {%4,%5,%6,%7}, {%8,%9}, {%0,%1,%2,%3};"
        : "+f"(d0), "+f"(d1), "+f"(d2), "+f"(d3)
        : "r"(a0), "r"(a1), "r"(a2), "r"(a3), "r"(b0), "r"(b1));
}
__device__ __forceinline__ void ldm_x4(uint32_t& r0, uint32_t& r1, uint32_t& r2, uint32_t& r3,
                                       uint32_t addr) {
    asm volatile("ldmatrix.sync.aligned.m8n8.x4.shared.b16 {%0,%1,%2,%3}, [%4];"
                 : "=r"(r0), "=r"(r1), "=r"(r2), "=r"(r3) : "r"(addr));
}

#define ASTR 72

// ============================================================
// prep: block 0 = classify + weight pre-split; blocks 1.. zero g_cnt
// ============================================================
__global__ void __launch_bounds__(256) k_prep(
    const float* q0, const float* q1, const float* q2, const float* q3,
    const int* ei32, const int* n2g32, int N,
    const float* __restrict__ lin_wv,    // [128, 64]
    const float* __restrict__ film_w)    // [64, 256]
{
    int t = threadIdx.x;
    if (blockIdx.x > 0) {
        int base = (blockIdx.x - 1) * 1024;
        for (int i = base + t; i < base + 1024 && i < N; i += 256) g_cnt[i] = 0;
        return;
    }
    __shared__ int scnt[4];
    __shared__ int sor[2];
    __shared__ const float* sg[2];
    __shared__ const float* sb[2];
    __shared__ float s_scale[128];
    if (t < 4) scnt[t] = 0;
    if (t < 2) sor[t] = 0;
    __syncthreads();
    const float* qs[4] = {q0, q1, q2, q3};
    if (t < 128) {
        #pragma unroll
        for (int j = 0; j < 4; j++)
            if (qs[j][t] < 0.3f) atomicAdd(&scnt[j], 1);
    }
    if (t < 64) atomicOr(&sor[0], ei32[2 * t + 1]);
    if (t < 32) {
        int st = (N - 2) | 1;
        atomicOr(&sor[1], n2g32[st - 2 * t]);
    }
    __syncthreads();
    if (t == 0) {
        int gi = 0, bi = 0;
        #pragma unroll
        for (int j = 0; j < 4; j++) {
            if (scnt[j] > 64) { if (bi < 2) sb[bi++] = qs[j]; }
            else              { if (gi < 2) sg[gi++] = qs[j]; }
        }
        if (gi < 2) { sg[0] = q0; sg[1] = q2; }
        if (bi < 2) { sb[0] = q1; sb[1] = q3; }
        d_gainp[0] = sg[0]; d_gainp[1] = sg[1];
        d_biasp[0] = sb[0]; d_biasp[1] = sb[1];
        d_ei64 = (sor[0] == 0) ? 1 : 0;
        d_n2g64 = (sor[1] == 0) ? 1 : 0;
    }
    __syncthreads();
    if (t < 128) {
        const float* wr = lin_wv + t * HID;
        float s2 = 0.f;
        #pragma unroll 8
        for (int k = 0; k < HID; k++) { float v = wr[k]; s2 += v * v; }
        s_scale[t] = sg[1][t] * rsqrtf(s2);
    }
    __syncthreads();
    for (int e = t; e < 128 * 4 * 4; e += 256) {
        int lc = e & 3;
        int kb16 = (e >> 2) & 3;
        int n = e >> 4;
        int k0 = kb16 * 16 + 2 * lc;
        float sc = s_scale[n];
        uint32_t bh0, bl0, bh1, bl1;
        bf16_split2(lin_wv[n * HID + k0] * sc,     lin_wv[n * HID + k0 + 1] * sc, bh0, bl0);
        bf16_split2(lin_wv[n * HID + k0 + 8] * sc, lin_wv[n * HID + k0 + 9] * sc, bh1, bl1);
        g_lwf[e] = make_uint4(bh0, bh1, bl0, bl1);
    }
    for (int e = t; e < 64 * 16 * 4; e += 256) {
        int lc = e & 3;
        int kb16 = (e >> 2) & 15;
        int n = e >> 6;
        int k0 = kb16 * 16 + 2 * lc;
        uint32_t bh0, bl0, bh1, bl1;
        bf16_split2(film_w[n * ND + k0],     film_w[n * ND + k0 + 1], bh0, bl0);
        bf16_split2(film_w[n * ND + k0 + 8], film_w[n * ND + k0 + 9], bh1, bl1);
        g_fwf[e] = make_uint4(bh0, bh1, bl0, bl1);
    }
}

// ============================================================
// cond projection -> gamma/beta. grid=(128, 8), 256 thr
// ============================================================
__global__ void __launch_bounds__(256) k_cond(
    const float* __restrict__ cf,
    const float* __restrict__ wv)
{
    int o = blockIdx.x;
    int t = threadIdx.x;
    __shared__ float sw[CD];
    __shared__ float red[8];
    const float* wr = wv + o * CD;

    float s2 = 0.f;
    for (int k = t; k < CD; k += 256) { float v = wr[k]; sw[k] = v; s2 += v * v; }
    #pragma unroll
    for (int d = 16; d; d >>= 1) s2 += __shfl_xor_sync(0xFFFFFFFFu, s2, d);
    if ((t & 31) == 0) red[t >> 5] = s2;
    __syncthreads();
    float norm2 = red[0] + red[1] + red[2] + red[3] + red[4] + red[5] + red[6] + red[7];
    float scale = d_gainp[0][o] * rsqrtf(norm2);
    float bias  = d_biasp[0][o];

    const int w = t >> 5, lane = t & 31;
    int row = blockIdx.y * 8 + w;
    const float* cfr = cf + row * CD;
    float acc = 0.f;
    #pragma unroll
    for (int k = lane; k < CD; k += 32) acc += cfr[k] * sw[k];
    #pragma unroll
    for (int d = 16; d; d >>= 1) acc += __shfl_xor_sync(0xFFFFFFFFu, acc, d);
    if (lane == 0) {
        float val = acc * scale + bias;
        if (o < HID) g_gamma[row * HID + o] = val + 1.0f;
        else         g_beta[row * HID + (o - HID)] = val;
    }
}

// ============================================================
// node transform: pre-split bf16 A planes + ldmatrix, bf16x3 MMA
// ============================================================
__global__ void __launch_bounds__(256) k_node(
    const float* __restrict__ feats,
    const float* __restrict__ film_b,
    const void*  __restrict__ n2g,
    int nNodes)
{
    __shared__ __align__(16) char sm[36864];

    const int t = threadIdx.x;
    const int node0 = blockIdx.x * 64;
    const int w = t >> 5, lane = t & 31;
    const int mg = w >> 1, ng = w & 1;
    const int lr = lane >> 2, lc = lane & 3;
    const int srow = t >> 4, sc4 = t & 15;

    const uint32_t smb = (uint32_t)__cvta_generic_to_shared(sm);
    const int lmRow = ((lane >> 3) & 1) * 8 + (lane & 7);
    const int lmCol = (lane >> 4) * 8;

    float c[4][4];
    #pragma unroll
    for (int j = 0; j < 4; j++)
        #pragma unroll
        for (int i = 0; i < 4; i++) c[j][i] = 0.f;

    auto stage_store = [&](int b, int row, int c0, float4 va) {
        uint32_t h01, l01, h23, l23;
        bf16_split2(va.x, va.y, h01, l01);
        bf16_split2(va.z, va.w, h23, l23);
        char* hp = sm + b * 18432 + (row * ASTR + c0) * 2;
        char* lp = hp + 9216;
        *(uint2*)hp = make_uint2(h01, h23);
        *(uint2*)lp = make_uint2(l01, l23);
    };

    #pragma unroll
    for (int it = 0; it < 4; it++) {
        int row = srow + it * 16;
        float4 va = (node0 + row < nNodes)
            ? *(const float4*)(feats + (size_t)(node0 + row) * ND + sc4 * 4)
            : make_float4(0.f, 0.f, 0.f, 0.f);
        stage_store(0, row, sc4 * 4, va);
    }
    __syncthreads();

    #pragma unroll
    for (int ch = 0; ch < 4; ch++) {
        const int b = ch & 1;
        float4 pf[4];
        if (ch < 3) {
            #pragma unroll
            for (int it = 0; it < 4; it++) {
                int row = srow + it * 16;
                int gk  = (ch + 1) * 64 + sc4 * 4;
                pf[it] = (node0 + row < nNodes)
                    ? *(const float4*)(feats + (size_t)(node0 + row) * ND + gk)
                    : make_float4(0.f, 0.f, 0.f, 0.f);
            }
        }
        #pragma unroll
        for (int kb = 0; kb < 4; kb++) {
            uint32_t aBase = smb + b * 18432
                           + ((mg * 16 + lmRow) * ASTR + kb * 16 + lmCol) * 2;
            uint32_t ah0, ah1, ah2, ah3, al0, al1, al2, al3;
            ldm_x4(ah0, ah1, ah2, ah3, aBase);
            ldm_x4(al0, al1, al2, al3, aBase + 9216);
            int gkb16 = ch * 4 + kb;
            #pragma unroll
            for (int j = 0; j < 4; j++) {
                int bn = ng * 32 + j * 8 + lr;
                uint4 B = __ldg(&g_fwf[(bn * 16 + gkb16) * 4 + lc]);
                mma_bf16(c[j][0], c[j][1], c[j][2], c[j][3], ah0, ah1, ah2, ah3, B.x, B.y);
                mma_bf16(c[j][0], c[j][1], c[j][2], c[j][3], ah0, ah1, ah2, ah3, B.z, B.w);
                mma_bf16(c[j][0], c[j][1], c[j][2], c[j][3], al0, al1, al2, al3, B.x, B.y);
            }
        }
        if (ch < 3) {
            __syncthreads();
            #pragma unroll
            for (int it = 0; it < 4; it++)
                stage_store((ch + 1) & 1, srow + it * 16, sc4 * 4, pf[it]);
        }
        __syncthreads();
    }

    float* sH = (float*)sm;
    {
        int row0 = mg * 16 + lr;
        #pragma unroll
        for (int j = 0; j < 4; j++) {
            int cb = ng * 32 + j * 8 + 2 * lc;
            sH[row0 * 68 + cb]           = c[j][0] + __ldg(&film_b[cb]);
            sH[row0 * 68 + cb + 1]       = c[j][1] + __ldg(&film_b[cb + 1]);
            sH[(row0 + 8) * 68 + cb]     = c[j][2] + __ldg(&film_b[cb]);
            sH[(row0 + 8) * 68 + cb + 1] = c[j][3] + __ldg(&film_b[cb + 1]);
        }
    }
    __syncthreads();

    // ---- LayerNorm + FiLM + relu -> bf16 hi/lo planes for GEMM2 ----
    {
        __nv_bfloat16* hi2 = (__nv_bfloat16*)(sm + 18432);
        __nv_bfloat16* lo2 = (__nv_bfloat16*)(sm + 27648);
        const int is64 = d_n2g64;
        #pragma unroll
        for (int r = 0; r < 8; r++) {
            int i = w * 8 + r;
            int node = node0 + i;
            float v0 = sH[i * 68 + lane];
            float v1 = sH[i * 68 + 32 + lane];
            float s = v0 + v1;
            #pragma unroll
            for (int d = 16; d; d >>= 1) s += __shfl_xor_sync(0xFFFFFFFFu, s, d);
            float mu = s * (1.0f / 64.0f);
            float d0 = v0 - mu, d1 = v1 - mu;
            float q = d0 * d0 + d1 * d1;
            #pragma unroll
            for (int d = 16; d; d >>= 1) q += __shfl_xor_sync(0xFFFFFFFFu, q, d);
            float rstd = rsqrtf(q * (1.0f / 64.0f) + 1e-5f);
            int idx = (node < nNodes) ? node : 0;
            int g = is64 ? (int)((const long long*)n2g)[idx]
                         : ((const int*)n2g)[idx];
            g &= (NB - 1);
            const float* gp = g_gamma + g * HID;
            const float* bp = g_beta + g * HID;
            float y0 = fmaxf(gp[lane]      * (d0 * rstd) + bp[lane],      0.f);
            float y1 = fmaxf(gp[lane + 32] * (d1 * rstd) + bp[lane + 32], 0.f);
            __nv_bfloat16 h0 = __float2bfloat16(y0);
            __nv_bfloat16 h1 = __float2bfloat16(y1);
            hi2[i * ASTR + lane]      = h0;
            hi2[i * ASTR + 32 + lane] = h1;
            lo2[i * ASTR + lane]      = __float2bfloat16(y0 - __bfloat162float(h0));
            lo2[i * ASTR + 32 + lane] = __float2bfloat16(y1 - __bfloat162float(h1));
        }
    }
    __syncthreads();

    // ---- GEMM2 ----
    {
        float c2[8][4];
        #pragma unroll
        for (int j = 0; j < 8; j++)
            #pragma unroll
            for (int i = 0; i < 4; i++) c2[j][i] = 0.f;

        #pragma unroll
        for (int kb = 0; kb < 4; kb++) {
            uint32_t aBase = smb + 18432
                           + ((mg * 16 + lmRow) * ASTR + kb * 16 + lmCol) * 2;
            uint32_t ah0, ah1, ah2, ah3, al0, al1, al2, al3;
            ldm_x4(ah0, ah1, ah2, ah3, aBase);
            ldm_x4(al0, al1, al2, al3, aBase + 9216);
            #pragma unroll
            for (int j = 0; j < 8; j++) {
                int bn = ng * 64 + j * 8 + lr;
                uint4 B = __ldg(&g_lwf[(bn * 4 + kb) * 4 + lc]);
                mma_bf16(c2[j][0], c2[j][1], c2[j][2], c2[j][3], ah0, ah1, ah2, ah3, B.x, B.y);
                mma_bf16(c2[j][0], c2[j][1], c2[j][2], c2[j][3], ah0, ah1, ah2, ah3, B.z, B.w);
                mma_bf16(c2[j][0], c2[j][1], c2[j][2], c2[j][3], al0, al1, al2, al3, B.x, B.y);
            }
        }
        const float* lb = d_biasp[1];
        __half2* xh2 = (__half2*)g_xh;
        int r0 = node0 + mg * 16 + lr;
        #pragma unroll
        for (int j = 0; j < 8; j++) {
            int cb = ng * 64 + j * 8 + 2 * lc;
            float b0 = __ldg(&lb[cb]), b1 = __ldg(&lb[cb + 1]);
            if (r0 < nNodes)
                xh2[(size_t)r0 * 64 + (cb >> 1)] =
                    __floats2half2_rn(c2[j][0] + b0, c2[j][1] + b1);
            if (r0 + 8 < nNodes)
                xh2[(size_t)(r0 + 8) * 64 + (cb >> 1)] =
                    __floats2half2_rn(c2[j][2] + b0, c2[j][3] + b1);
        }
    }
}

// ============================================================
// CSR build — hist/fill vectorized: 4 edges per thread
// ============================================================
__global__ void k_hist(const void* __restrict__ eiv, int E, int nNodes) {
    int e4 = (blockIdx.x * blockDim.x + threadIdx.x) * 4;
    if (e4 >= E) return;
    if (d_ei64) {
        const long long* ei = (const long long*)eiv;
        #pragma unroll
        for (int u = 0; u < 4; u++) {
            if (e4 + u < E) {
                int dst = (int)ei[(size_t)E + e4 + u];
                if ((unsigned)dst < (unsigned)nNodes) atomicAdd(&g_cnt[dst], 1);
            }
        }
    } else {
        const int* ei = (const int*)eiv;
        if (e4 + 3 < E && ((E & 3) == 0)) {
            int4 d4 = *(const int4*)(ei + (size_t)E + e4);
            if ((unsigned)d4.x < (unsigned)nNodes) atomicAdd(&g_cnt[d4.x], 1);
            if ((unsigned)d4.y < (unsigned)nNodes) atomicAdd(&g_cnt[d4.y], 1);
            if ((unsigned)d4.z < (unsigned)nNodes) atomicAdd(&g_cnt[d4.z], 1);
            if ((unsigned)d4.w < (unsigned)nNodes) atomicAdd(&g_cnt[d4.w], 1);
        } else {
            #pragma unroll
            for (int u = 0; u < 4; u++) {
                if (e4 + u < E) {
                    int dst = ei[(size_t)E + e4 + u];
                    if ((unsigned)dst < (unsigned)nNodes) atomicAdd(&g_cnt[dst], 1);
                }
            }
        }
    }
}

__global__ void __launch_bounds__(1024) k_scan1(int n) {
    __shared__ int s[1024];
    int i = blockIdx.x * 1024 + threadIdx.x;
    int v = (i < n) ? g_cnt[i] : 0;
    s[threadIdx.x] = v;
    __syncthreads();
    #pragma unroll
    for (int d = 1; d < 1024; d <<= 1) {
        int t = (threadIdx.x >= d) ? s[threadIdx.x - d] : 0;
        __syncthreads();
        s[threadIdx.x] += t;
        __syncthreads();
    }
    if (i < n) g_excl[i] = s[threadIdx.x] - v;
    if (threadIdx.x == 1023) g_bsum[blockIdx.x] = s[1023];
}

__global__ void __launch_bounds__(256) k_scan3(int n) {
    __shared__ int sbase;
    int seg = (blockIdx.x * 256) >> 10;
    if (threadIdx.x < 32) {
        int partial = 0;
        for (int k = threadIdx.x; k < seg; k += 32) partial += g_bsum[k];
        #pragma unroll
        for (int d = 16; d; d >>= 1) partial += __shfl_xor_sync(0xFFFFFFFFu, partial, d);
        if (threadIdx.x == 0) sbase = partial;
    }
    __syncthreads();
    int i = blockIdx.x * 256 + threadIdx.x;
    if (i >= n) return;
    int st = g_excl[i] + sbase;
    g_start[i] = st;
    g_pos[i] = st;
}

__global__ void k_fill(const void* __restrict__ eiv, int E, int nNodes) {
    int e4 = (blockIdx.x * blockDim.x + threadIdx.x) * 4;
    if (e4 >= E) return;
    if (d_ei64) {
        const long long* ei = (const long long*)eiv;
        #pragma unroll
        for (int u = 0; u < 4; u++) {
            if (e4 + u < E) {
                int src = (int)ei[e4 + u];
                int dst = (int)ei[(size_t)E + e4 + u];
                if ((unsigned)src < (unsigned)nNodes && (unsigned)dst < (unsigned)nNodes) {
                    int p = atomicAdd(&g_pos[dst], 1);
                    g_srcs[p] = src;
                }
            }
        }
    } else {
        const int* ei = (const int*)eiv;
        if (e4 + 3 < E && ((E & 3) == 0)) {
            int4 s4 = *(const int4*)(ei + e4);
            int4 d4 = *(const int4*)(ei + (size_t)E + e4);
            int ss[4] = {s4.x, s4.y, s4.z, s4.w};
            int dd[4] = {d4.x, d4.y, d4.z, d4.w};
            #pragma unroll
            for (int u = 0; u < 4; u++) {
                if ((unsigned)ss[u] < (unsigned)nNodes && (unsigned)dd[u] < (unsigned)nNodes) {
                    int p = atomicAdd(&g_pos[dd[u]], 1);
                    g_srcs[p] = ss[u];
                }
            }
        } else {
            #pragma unroll
            for (int u = 0; u < 4; u++) {
                if (e4 + u < E) {
                    int src = ei[e4 + u];
                    int dst = ei[(size_t)E + e4 + u];
                    if ((unsigned)src < (unsigned)nNodes && (unsigned)dst < (unsigned)nNodes) {
                        int p = atomicAdd(&g_pos[dst], 1);
                        g_srcs[p] = src;
                    }
                }
            }
        }
    }
}

// ============================================================
// gather: one warp per destination node, 8-deep MLP
// ============================================================
__global__ void __launch_bounds__(256) k_gather(float4* __restrict__ out4, int nNodes) {
    int warp = (blockIdx.x * blockDim.x + threadIdx.x) >> 5;
    if (warp >= nNodes) return;
    int lane = threadIdx.x & 31;
    int start = g_start[warp];
    int deg = g_cnt[warp];
    const uint2* x2 = (const uint2*)g_xh;

    float4 acc = make_float4(0.f, 0.f, 0.f, 0.f);
    int j = 0;
    for (; j + 8 <= deg; j += 8) {
        int ss[8];
        #pragma unroll
        for (int u = 0; u < 8; u++) ss[u] = __ldg(&g_srcs[start + j + u]);
        uint2 uu[8];
        #pragma unroll
        for (int u = 0; u < 8; u++) uu[u] = __ldg(&x2[(size_t)ss[u] * 32 + lane]);
        #pragma unroll
        for (int u = 0; u < 8; u++) {
            float2 a = __half22float2(*(__half2*)&uu[u].x);
            float2 b = __half22float2(*(__half2*)&uu[u].y);
            acc.x += a.x; acc.y += a.y; acc.z += b.x; acc.w += b.y;
        }
    }
    for (; j + 4 <= deg; j += 4) {
        int ss[4];
        #pragma unroll
        for (int u = 0; u < 4; u++) ss[u] = __ldg(&g_srcs[start + j + u]);
        uint2 uu[4];
        #pragma unroll
        for (int u = 0; u < 4; u++) uu[u] = __ldg(&x2[(size_t)ss[u] * 32 + lane]);
        #pragma unroll
        for (int u = 0; u < 4; u++) {
            float2 a = __half22float2(*(__half2*)&uu[u].x);
            float2 b = __half22float2(*(__half2*)&uu[u].y);
            acc.x += a.x; acc.y += a.y; acc.z += b.x; acc.w += b.y;
        }
    }
    for (; j < deg; j++) {
        int s0 = __ldg(&g_srcs[start + j]);
        uint2 u0 = __ldg(&x2[(size_t)s0 * 32 + lane]);
        float2 a0 = __half22float2(*(__half2*)&u0.x), b0 = __half22float2(*(__half2*)&u0.y);
        acc.x += a0.x; acc.y += a0.y; acc.z += b0.x; acc.w += b0.y;
    }
    float s = 1.0f / (float)max(deg, 1);
    float4 o;
    o.x = fmaxf(acc.x * s, 0.f);
    o.y = fmaxf(acc.y * s, 0.f);
    o.z = fmaxf(acc.z * s, 0.f);
    o.w = fmaxf(acc.w * s, 0.f);
    out4[(size_t)warp * 32 + lane] = o;
}

// ============================================================
extern "C" void kernel_launch(void* const* d_in, const int* in_sizes, int n_in,
                              void* d_out, int out_size)
{
    const float *node_feats = 0, *cond_feats = 0, *cond_w_v = 0;
    const float *film_w = 0, *film_b = 0, *lin_w_v = 0;
    const void  *edge_index = 0, *node2graph = 0;
    const float *quad[4] = {0, 0, 0, 0};
    int nq = 0;
    int nNodes = NMAX, E = EMAX;

    for (int i = 0; i < n_in; i++) {
        int s = in_sizes[i];
        const void* p = d_in[i];
        switch (s) {
            case NMAX * ND:   node_feats = (const float*)p; nNodes = s / ND; break;
            case 2 * EMAX:    edge_index = p; E = s / 2; break;
            case OD * CD:     cond_w_v   = (const float*)p; break;
            case NB * CD:     cond_feats = (const float*)p; break;
            case HID * ND:    film_w     = (const float*)p; break;
            case OD * HID:    lin_w_v    = (const float*)p; break;
            case NMAX:        node2graph = p; break;
            case HID:         film_b     = (const float*)p; break;
            case OD:          if (nq < 4) quad[nq++] = (const float*)p; break;
            default: break;
        }
    }
    if (!node_feats || !edge_index || !node2graph || nq < 4) return;

    float* out = (float*)d_out;

    static cudaStream_t s_aux = 0;
    static cudaEvent_t s_ev0 = 0, s_ev1 = 0;
    static int s_tried = 0;
    if (!s_tried) {
        s_tried = 1;
        if (cudaStreamCreateWithFlags(&s_aux, cudaStreamNonBlocking) != cudaSuccess) s_aux = 0;
        if (s_aux) {
            if (cudaEventCreateWithFlags(&s_ev0, cudaEventDisableTiming) != cudaSuccess) s_ev0 = 0;
            if (cudaEventCreateWithFlags(&s_ev1, cudaEventDisableTiming) != cudaSuccess) s_ev1 = 0;
            if (!s_ev0 || !s_ev1) s_aux = 0;
        }
    }

    const int prepBlocks = 1 + (nNodes + 1023) / 1024;
    const int nodeBlocks = (nNodes + 63) / 64;
    const int edgeBlocks4 = ((E + 3) / 4 + 255) / 256;
    const int nb = (nNodes + 1023) / 1024;
    dim3 condGrid(OD, 8);
    const long long gwork = (long long)nNodes * 32;
    const int gatherBlocks = (int)((gwork + 255) / 256);

    if (s_aux) {
        k_prep<<<prepBlocks, 256>>>(quad[0], quad[1], quad[2], quad[3],
                                    (const int*)edge_index, (const int*)node2graph,
                                    nNodes, lin_w_v, film_w);
        cudaEventRecord(s_ev0, 0);
        cudaStreamWaitEvent(s_aux, s_ev0, 0);
        k_hist<<<edgeBlocks4, 256, 0, s_aux>>>(edge_index, E, nNodes);
        k_scan1<<<nb, 1024, 0, s_aux>>>(nNodes);
        k_scan3<<<(nNodes + 255) / 256, 256, 0, s_aux>>>(nNodes);
        k_fill<<<edgeBlocks4, 256, 0, s_aux>>>(edge_index, E, nNodes);
        cudaEventRecord(s_ev1, s_aux);
        k_cond<<<condGrid, 256>>>(cond_feats, cond_w_v);
        k_node<<<nodeBlocks, 256>>>(node_feats, film_b, node2graph, nNodes);
        cudaStreamWaitEvent(0, s_ev1, 0);
        k_gather<<<gatherBlocks, 256>>>((float4*)out, nNodes);
    } else {
        k_prep<<<prepBlocks, 256>>>(quad[0], quad[1], quad[2], quad[3],
                                    (const int*)edge_index, (const int*)node2graph,
                                    nNodes, lin_w_v, film_w);
        k_cond<<<condGrid, 256>>>(cond_feats, cond_w_v);
        k_hist<<<edgeBlocks4, 256>>>(edge_index, E, nNodes);
        k_scan1<<<nb, 1024>>>(nNodes);
        k_scan3<<<(nNodes + 255) / 256, 256>>>(nNodes);
        k_fill<<<edgeBlocks4, 256>>>(edge_index, E, nNodes);
        k_node<<<nodeBlocks, 256>>>(node_feats, film_b, node2graph, nNodes);
        k_gather<<<gatherBlocks, 256>>>((float4*)out, nNodes);
    }
}